// round 13
// baseline (speedup 1.0000x reference)
#include <cuda_runtime.h>
#include <cstdint>

#define B_NO   8
#define T_DATA 5000
#define E_NO   2000
#define SUB_NO 20
#define HID_NO 10
#define SH_NO  200
#define T_NO   50
#define NCH    1600

#define PCH 8
#define NCHUNKS 625        // 5000 / 8

typedef unsigned long long ull;

__device__ float g_CT[E_NO * SUB_NO];
__device__ float g_syn[B_NO * SUB_NO * T_DATA];
__device__ float g_conv[B_NO * SH_NO * (size_t)T_DATA];
__device__ float g_ybuf[B_NO * SH_NO * (size_t)T_DATA];

__device__ __forceinline__ ull pk2(float x, float y) {
    ull r;
    asm("mov.b64 %0, {%1, %2};" : "=l"(r) : "f"(x), "f"(y));
    return r;
}
__device__ __forceinline__ ull ffma2(ull a, ull b, ull c) {
    ull d;
    asm("fma.rn.f32x2 %0, %1, %2, %3;" : "=l"(d) : "l"(a), "l"(b), "l"(c));
    return d;
}
__device__ __forceinline__ ull add2(ull a, ull b) {
    ull d;
    asm("add.rn.f32x2 %0, %1, %2;" : "=l"(d) : "l"(a), "l"(b));
    return d;
}
__device__ __forceinline__ float2 upk2(ull v) {
    float2 f;
    asm("mov.b64 {%0, %1}, %2;" : "=f"(f.x), "=f"(f.y) : "l"(v));
    return f;
}
__device__ __forceinline__ float tanh_hw(float x) {
    float y;
    asm("tanh.approx.f32 %0, %1;" : "=f"(y) : "f"(x));
    return y;
}

// ---------- 1. prep ----------
__global__ void prep_kernel(const float* __restrict__ C, const float* __restrict__ Esc) {
    int i = blockIdx.x * 256 + threadIdx.x;
    if (i >= E_NO * SUB_NO) return;
    int e = i / SUB_NO, s = i % SUB_NO;
    g_CT[i] = C[s * E_NO + e] * expf(Esc[e]);
}

// ---------- 2. GEMM (R5-proven) ----------
#define ETILE 16
#define GROWS 128
#define GTHR  64
#define NTILE (E_NO / ETILE)

__global__ void __launch_bounds__(GTHR) gemm_kernel(const float* __restrict__ S_e) {
    __shared__ float sS[2][GROWS * 17];
    __shared__ float sC[2][ETILE * 20];
    const int b = blockIdx.y;
    const int t0 = blockIdx.x * GROWS;
    const int tid = threadIdx.x;
    const float* Sb = S_e + (size_t)b * T_DATA * E_NO;

    ull acc0[10], acc1[10];
#pragma unroll
    for (int s = 0; s < 10; s++) { acc0[s] = 0ull; acc1[s] = 0ull; }

    float4 pf[8];
    float pc[5];

#define LDG_TILE(E0)                                                        \
    {                                                                       \
        _Pragma("unroll")                                                   \
        for (int kk = 0; kk < 8; kk++) {                                    \
            int q = tid + kk * GTHR;                                        \
            int r = q >> 2, c4 = q & 3;                                     \
            int t = t0 + r;                                                 \
            pf[kk] = (t < T_DATA)                                           \
                ? *(const float4*)(Sb + (size_t)t * E_NO + (E0) + c4 * 4)   \
                : make_float4(0.f, 0.f, 0.f, 0.f);                          \
        }                                                                   \
        _Pragma("unroll")                                                   \
        for (int m = 0; m < 5; m++) pc[m] = g_CT[(E0) * 20 + tid * 5 + m];  \
    }

#define STS_TILE(BUF)                                                       \
    {                                                                       \
        _Pragma("unroll")                                                   \
        for (int kk = 0; kk < 8; kk++) {                                    \
            int q = tid + kk * GTHR;                                        \
            int r = q >> 2, c4 = q & 3;                                     \
            float* d = &sS[BUF][r * 17 + c4 * 4];                           \
            d[0] = pf[kk].x; d[1] = pf[kk].y;                               \
            d[2] = pf[kk].z; d[3] = pf[kk].w;                               \
        }                                                                   \
        _Pragma("unroll")                                                   \
        for (int m = 0; m < 5; m++) sC[BUF][tid * 5 + m] = pc[m];           \
    }

    LDG_TILE(0);
    STS_TILE(0);
    LDG_TILE(ETILE);
    __syncthreads();

    for (int it = 0; it < NTILE; it++) {
        const int cur = it & 1;
#pragma unroll
        for (int j = 0; j < ETILE; j++) {
            ull cp[10];
#pragma unroll
            for (int s = 0; s < 10; s++)
                cp[s] = *(const ull*)&sC[cur][j * 20 + 2 * s];
            float v0 = sS[cur][tid * 17 + j];
            float v1 = sS[cur][(tid + GTHR) * 17 + j];
            ull v0p = pk2(v0, v0), v1p = pk2(v1, v1);
#pragma unroll
            for (int s = 0; s < 10; s++) {
                acc0[s] = ffma2(v0p, cp[s], acc0[s]);
                acc1[s] = ffma2(v1p, cp[s], acc1[s]);
            }
        }
        if (it < NTILE - 1) {
            STS_TILE(cur ^ 1);
            if (it < NTILE - 2) LDG_TILE((it + 2) * ETILE);
            __syncthreads();
        }
    }

    int ta = t0 + tid;
    if (ta < T_DATA) {
#pragma unroll
        for (int s = 0; s < 10; s++) {
            float2 f = upk2(acc0[s]);
            g_syn[((size_t)b * SUB_NO + 2 * s)     * T_DATA + ta] = f.x;
            g_syn[((size_t)b * SUB_NO + 2 * s + 1) * T_DATA + ta] = f.y;
        }
    }
    int tb = t0 + GTHR + tid;
    if (tb < T_DATA) {
#pragma unroll
        for (int s = 0; s < 10; s++) {
            float2 f = upk2(acc1[s]);
            g_syn[((size_t)b * SUB_NO + 2 * s)     * T_DATA + tb] = f.x;
            g_syn[((size_t)b * SUB_NO + 2 * s + 1) * T_DATA + tb] = f.y;
        }
    }
}

// ---------- 3. depthwise causal conv (time-halved) ----------
#define CHALF 2500
__global__ void __launch_bounds__(256) conv_kernel(const float* __restrict__ W1) {
    const int bs = blockIdx.x;
    const int half = bs & 1;
    const int bsub = bs >> 1;
    const int b = bsub / SUB_NO, s = bsub % SUB_NO;
    const int t0 = half * CHALF;
    __shared__ float ss[T_NO - 1 + CHALF];
    const int tid = threadIdx.x;

    const float* sp = g_syn + ((size_t)b * SUB_NO + s) * T_DATA;
    for (int i = tid; i < T_NO - 1 + CHALF; i += 256) {
        int gt = t0 - (T_NO - 1) + i;
        ss[i] = (gt >= 0) ? sp[gt] : 0.0f;
    }
    __syncthreads();

    for (int h = 0; h < HID_NO; h++) {
        const int c = s * HID_NO + h;
        float w[T_NO];
#pragma unroll
        for (int i = 0; i < T_NO; i++) w[i] = __ldg(&W1[c * T_NO + i]);
        float* cp = g_conv + ((size_t)(b * SH_NO + c)) * T_DATA + t0;
        for (int t = tid; t < CHALF; t += 256) {
            float acc = 0.0f;
#pragma unroll
            for (int tau = 0; tau < T_NO; tau++)
                acc = fmaf(ss[T_NO - 1 + t - tau], w[tau], acc);
            cp[t] = acc;
        }
    }
}

// ---------- 4. recurrence: P=8 lockstep, smem y-ring helpers ----------
// W0 (A): taps 1..15 serial, 4 step-pairs/chunk.
// h1 (w1): taps 16..27 + output stores.  h2 (w2): taps 28..39.
// h3 (w3): taps 40..50 + conv + bias.
// y-ring: s_y[8][32][5] ull; slot = chunk & 7; [q] = steps (2q, 2q+1), q<4.
template<int TB0, int NT, int MODE>   // MODE: 1 = stores, 2 = conv+bias
__device__ __forceinline__ void run_helper(
    int lane, int ch, int c, int widx,
    const float* __restrict__ Wh, const float* __restrict__ b1,
    const float* __restrict__ W2l,
    ull (*s_y)[32][5], ull (*sp)[32][5])
{
    constexpr int KB  = (TB0 + NT + 6) / 8 - 1;    // base chunk = k - KB
    constexpr int OFF = 8 * KB + 8 - TB0;          // ya idx = OFF + j - u

    float w[NT];
#pragma unroll
    for (int u = 0; u < NT; u++) w[u] = __ldg(&Wh[c * T_NO + TB0 - 1 + u]);
    const float ew2  = (MODE == 1) ? expf(W2l[c]) : 0.0f;
    const float bias = (MODE == 2) ? b1[c] : 0.0f;
    const float* cv = g_conv + (size_t)ch * T_DATA;
    float* yo = g_ybuf + (size_t)ch * T_DATA;

    // zero ring slots 2..7 (chunks -6..-1): helper widx zeroes slots 2w, 2w+1
    {
        int s0 = 2 * widx;                         // widx = 1,2,3 -> slots 2..7
#pragma unroll
        for (int q = 0; q < 5; q++) {
            s_y[s0][lane][q] = 0ull;
            s_y[s0 + 1][lane][q] = 0ull;
        }
    }

    float cn[PCH];
    // P[0]
    {
        float* pr = (float*)&sp[0][lane][0];
        if (MODE == 2) {
#pragma unroll
            for (int j = 0; j < PCH; j += 2) {
                float2 t = *(const float2*)(cv + j);
                pr[j] = t.x + bias; pr[j + 1] = t.y + bias;
            }
        } else {
#pragma unroll
            for (int j = 0; j < PCH; j++) pr[j] = 0.0f;
        }
    }
    __syncthreads();                               // bar 0
    // P[1] (no y history yet)
    {
        float* pr = (float*)&sp[1][lane][0];
        if (MODE == 2) {
#pragma unroll
            for (int j = 0; j < PCH; j += 2) {
                float2 t = *(const float2*)(cv + PCH + j);
                pr[j] = t.x + bias; pr[j + 1] = t.y + bias;
            }
#pragma unroll
            for (int j = 0; j < PCH; j += 2) {
                float2 t = *(const float2*)(cv + 2 * PCH + j);
                cn[j] = t.x; cn[j + 1] = t.y;
            }
        } else {
#pragma unroll
            for (int j = 0; j < PCH; j++) pr[j] = 0.0f;
        }
    }
    __syncthreads();                               // bar 1

    for (int k = 1; k <= NCHUNKS - 2; k++) {
        // gather history: chunks k-KB .. k-KB+2 -> ya[0..23]
        float ya[24];
        {
            const ull* r0 = &s_y[(k - KB)     & 7][lane][0];
            const ull* r1 = &s_y[(k - KB + 1) & 7][lane][0];
            const ull* r2 = &s_y[(k - KB + 2) & 7][lane][0];
#pragma unroll
            for (int q = 0; q < 4; q++) {
                float2 t = upk2(r0[q]); ya[2 * q] = t.x;      ya[2 * q + 1] = t.y;
            }
#pragma unroll
            for (int q = 0; q < 4; q++) {
                float2 t = upk2(r1[q]); ya[8 + 2 * q] = t.x;  ya[8 + 2 * q + 1] = t.y;
            }
#pragma unroll
            for (int q = 0; q < 4; q++) {
                float2 t = upk2(r2[q]); ya[16 + 2 * q] = t.x; ya[16 + 2 * q + 1] = t.y;
            }
        }
        if (MODE == 1) {                           // store chunk k-1 (= ya[16..23])
            float* yob = yo + (size_t)(k - 1) * PCH;
#pragma unroll
            for (int q = 0; q < 4; q++)
                *(float2*)(yob + 2 * q) =
                    make_float2(ew2 * ya[16 + 2 * q], ew2 * ya[16 + 2 * q + 1]);
        }

        float part[PCH];
        if (MODE == 2) {
#pragma unroll
            for (int j = 0; j < PCH; j++) part[j] = cn[j] + bias;
        } else {
#pragma unroll
            for (int j = 0; j < PCH; j++) part[j] = 0.0f;
        }
#pragma unroll
        for (int j = 0; j < PCH; j++)
#pragma unroll
            for (int u = 0; u < NT; u++)
                part[j] = fmaf(ya[OFF + j - u], w[u], part[j]);

        float* pw = (float*)&sp[(k + 1) & 1][lane][0];
#pragma unroll
        for (int j = 0; j < PCH; j++) pw[j] = part[j];

        if (MODE == 2) {                           // prefetch conv chunk k+2
            int nk = (k + 2 <= NCHUNKS - 1) ? (k + 2) : (NCHUNKS - 1);
#pragma unroll
            for (int j = 0; j < PCH; j += 2) {
                float2 t = *(const float2*)(cv + nk * PCH + j);
                cn[j] = t.x; cn[j + 1] = t.y;
            }
        }
        __syncthreads();                           // bars 2..624
    }

    // epoch 624: store chunk 623
    if (MODE == 1) {
        const ull* yr = &s_y[(NCHUNKS - 2) & 7][lane][0];
        float* yob = yo + (size_t)(NCHUNKS - 2) * PCH;
#pragma unroll
        for (int q = 0; q < 4; q++) {
            float2 t = upk2(yr[q]);
            *(float2*)(yob + 2 * q) = make_float2(ew2 * t.x, ew2 * t.y);
        }
    }
    __syncthreads();                               // bar 625
    if (MODE == 1) {                               // store chunk 624
        const ull* yr = &s_y[(NCHUNKS - 1) & 7][lane][0];
        float* yob = yo + (size_t)(NCHUNKS - 1) * PCH;
#pragma unroll
        for (int q = 0; q < 4; q++) {
            float2 t = upk2(yr[q]);
            *(float2*)(yob + 2 * q) = make_float2(ew2 * t.x, ew2 * t.y);
        }
    }
}

__global__ void __launch_bounds__(128, 1) recur_kernel(const float* __restrict__ Wh,
                                                       const float* __restrict__ b1,
                                                       const float* __restrict__ W2l) {
    __shared__ ull s_y[8][32][5];
    __shared__ ull s_p1[2][32][5];
    __shared__ ull s_p2[2][32][5];
    __shared__ ull s_p3[2][32][5];

    const int lane = threadIdx.x & 31;
    const int warp = threadIdx.x >> 5;
    const int ch = blockIdx.x * 32 + lane;
    const int c = ch % SH_NO;

    if (warp == 0) {
        // ---- warp A: taps 1..15 ----
        float w[17];
#pragma unroll
        for (int i = 0; i < 15; i++) w[i] = __ldg(&Wh[c * T_NO + i]);
        w[15] = 0.0f; w[16] = 0.0f;
        const float w0 = w[0];
        ull wp0[8], wp1[7];
#pragma unroll
        for (int i = 0; i < 8; i++) wp0[i] = pk2(w[2 * i], w[2 * i + 1]);
#pragma unroll
        for (int i = 0; i < 7; i++) wp1[i] = pk2(w[2 * i + 1], w[2 * i + 2]);

        ull A2[12];                                // 24-step scatter window
#pragma unroll
        for (int m = 0; m < 12; m++) A2[m] = 0ull;

        __syncthreads();                           // bar 0

        for (int k = 0; k < NCHUNKS; k++) {
            const ull* pp1 = &s_p1[k & 1][lane][0];
            const ull* pp2 = &s_p2[k & 1][lane][0];
            const ull* pp3 = &s_p3[k & 1][lane][0];
#pragma unroll
            for (int m = 0; m < 4; m++)
                A2[m] = add2(A2[m], add2(add2(pp1[m], pp2[m]), pp3[m]));

            ull* yrow = &s_y[k & 7][lane][0];
#pragma unroll
            for (int pp = 0; pp < 4; pp++) {
                float2 a = upk2(A2[pp]);
                float y0 = tanh_hw(a.x);
                float v1 = fmaf(y0, w0, a.y);
                float y1 = tanh_hw(v1);
                yrow[pp] = pk2(y0, y1);
                ull yy0 = pk2(y0, y0);
                ull yy1 = pk2(y1, y1);
#pragma unroll
                for (int i = 0; i < 8; i++)
                    A2[pp + 1 + i] = ffma2(yy1, wp0[i], A2[pp + 1 + i]);
#pragma unroll
                for (int i = 0; i < 7; i++)
                    A2[pp + 1 + i] = ffma2(yy0, wp1[i], A2[pp + 1 + i]);
            }
#pragma unroll
            for (int m = 0; m < 8; m++) A2[m] = A2[m + 4];
#pragma unroll
            for (int m = 8; m < 12; m++) A2[m] = 0ull;
            __syncthreads();                       // bars 1..625
        }
    } else if (warp == 1) {
        run_helper<16, 12, 1>(lane, ch, c, 1, Wh, b1, W2l, s_y, s_p1);
    } else if (warp == 2) {
        run_helper<28, 12, 0>(lane, ch, c, 2, Wh, b1, W2l, s_y, s_p2);
    } else {
        run_helper<40, 11, 2>(lane, ch, c, 3, Wh, b1, W2l, s_y, s_p3);
    }
}

// ---------- 5. reduce ----------
__global__ void __launch_bounds__(256) reduce_kernel(const float* __restrict__ V_o,
                                                     float* __restrict__ out) {
    int idx = blockIdx.x * 256 + threadIdx.x;
    if (idx >= B_NO * T_DATA) return;
    int b = idx / T_DATA, t = idx % T_DATA;
    const float* p = g_ybuf + (size_t)b * SH_NO * T_DATA + t;
    float a = V_o[0];
#pragma unroll 10
    for (int c = 0; c < SH_NO; c++) a += p[(size_t)c * T_DATA];
    out[idx] = a;
}

extern "C" void kernel_launch(void* const* d_in, const int* in_sizes, int n_in,
                              void* d_out, int out_size) {
    const float* S_e     = (const float*)d_in[0];
    const float* C_syn_e = (const float*)d_in[2];
    const float* E_scale = (const float*)d_in[4];
    const float* W1      = (const float*)d_in[6];
    const float* W2      = (const float*)d_in[7];
    const float* b1      = (const float*)d_in[8];
    const float* Wh      = (const float*)d_in[9];
    const float* V_o     = (const float*)d_in[11];
    float* out = (float*)d_out;

    prep_kernel<<<(E_NO * SUB_NO + 255) / 256, 256>>>(C_syn_e, E_scale);
    dim3 gg((T_DATA + GROWS - 1) / GROWS, B_NO);
    gemm_kernel<<<gg, GTHR>>>(S_e);
    conv_kernel<<<B_NO * SUB_NO * 2, 256>>>(W1);
    recur_kernel<<<NCH / 32, 128>>>(Wh, b1, W2);
    reduce_kernel<<<(B_NO * T_DATA + 255) / 256, 256>>>(V_o, out);
}

// round 14
// speedup vs baseline: 1.0959x; 1.0959x over previous
#include <cuda_runtime.h>
#include <cstdint>

#define B_NO   8
#define T_DATA 5000
#define E_NO   2000
#define SUB_NO 20
#define HID_NO 10
#define SH_NO  200
#define T_NO   50
#define NCH    1600

#define PCH 10
#define NCHUNKS 500

typedef unsigned long long ull;

__device__ float g_CT[E_NO * SUB_NO];
__device__ float g_syn[B_NO * SUB_NO * T_DATA];
__device__ float g_conv[B_NO * SH_NO * (size_t)T_DATA];
__device__ float g_ybuf[B_NO * SH_NO * (size_t)T_DATA];

__device__ __forceinline__ ull pk2(float x, float y) {
    ull r;
    asm("mov.b64 %0, {%1, %2};" : "=l"(r) : "f"(x), "f"(y));
    return r;
}
__device__ __forceinline__ ull ffma2(ull a, ull b, ull c) {
    ull d;
    asm("fma.rn.f32x2 %0, %1, %2, %3;" : "=l"(d) : "l"(a), "l"(b), "l"(c));
    return d;
}
__device__ __forceinline__ ull add2(ull a, ull b) {
    ull d;
    asm("add.rn.f32x2 %0, %1, %2;" : "=l"(d) : "l"(a), "l"(b));
    return d;
}
__device__ __forceinline__ float2 upk2(ull v) {
    float2 f;
    asm("mov.b64 {%0, %1}, %2;" : "=f"(f.x), "=f"(f.y) : "l"(v));
    return f;
}
__device__ __forceinline__ float tanh_hw(float x) {
    float y;
    asm("tanh.approx.f32 %0, %1;" : "=f"(y) : "f"(x));
    return y;
}

// ---------- 1. prep ----------
__global__ void prep_kernel(const float* __restrict__ C, const float* __restrict__ Esc) {
    int i = blockIdx.x * 256 + threadIdx.x;
    if (i >= E_NO * SUB_NO) return;
    int e = i / SUB_NO, s = i % SUB_NO;
    g_CT[i] = C[s * E_NO + e] * expf(Esc[e]);
}

// ---------- 2. GEMM (R5-proven: 64 thr, 2 rows/thread, double-buffered) ----------
#define ETILE 16
#define GROWS 128
#define GTHR  64
#define NTILE (E_NO / ETILE)

__global__ void __launch_bounds__(GTHR) gemm_kernel(const float* __restrict__ S_e) {
    __shared__ float sS[2][GROWS * 17];
    __shared__ float sC[2][ETILE * 20];
    const int b = blockIdx.y;
    const int t0 = blockIdx.x * GROWS;
    const int tid = threadIdx.x;
    const float* Sb = S_e + (size_t)b * T_DATA * E_NO;

    ull acc0[10], acc1[10];
#pragma unroll
    for (int s = 0; s < 10; s++) { acc0[s] = 0ull; acc1[s] = 0ull; }

    float4 pf[8];
    float pc[5];

#define LDG_TILE(E0)                                                        \
    {                                                                       \
        _Pragma("unroll")                                                   \
        for (int kk = 0; kk < 8; kk++) {                                    \
            int q = tid + kk * GTHR;                                        \
            int r = q >> 2, c4 = q & 3;                                     \
            int t = t0 + r;                                                 \
            pf[kk] = (t < T_DATA)                                           \
                ? *(const float4*)(Sb + (size_t)t * E_NO + (E0) + c4 * 4)   \
                : make_float4(0.f, 0.f, 0.f, 0.f);                          \
        }                                                                   \
        _Pragma("unroll")                                                   \
        for (int m = 0; m < 5; m++) pc[m] = g_CT[(E0) * 20 + tid * 5 + m];  \
    }

#define STS_TILE(BUF)                                                       \
    {                                                                       \
        _Pragma("unroll")                                                   \
        for (int kk = 0; kk < 8; kk++) {                                    \
            int q = tid + kk * GTHR;                                        \
            int r = q >> 2, c4 = q & 3;                                     \
            float* d = &sS[BUF][r * 17 + c4 * 4];                           \
            d[0] = pf[kk].x; d[1] = pf[kk].y;                               \
            d[2] = pf[kk].z; d[3] = pf[kk].w;                               \
        }                                                                   \
        _Pragma("unroll")                                                   \
        for (int m = 0; m < 5; m++) sC[BUF][tid * 5 + m] = pc[m];           \
    }

    LDG_TILE(0);
    STS_TILE(0);
    LDG_TILE(ETILE);
    __syncthreads();

    for (int it = 0; it < NTILE; it++) {
        const int cur = it & 1;
#pragma unroll
        for (int j = 0; j < ETILE; j++) {
            ull cp[10];
#pragma unroll
            for (int s = 0; s < 10; s++)
                cp[s] = *(const ull*)&sC[cur][j * 20 + 2 * s];
            float v0 = sS[cur][tid * 17 + j];
            float v1 = sS[cur][(tid + GTHR) * 17 + j];
            ull v0p = pk2(v0, v0), v1p = pk2(v1, v1);
#pragma unroll
            for (int s = 0; s < 10; s++) {
                acc0[s] = ffma2(v0p, cp[s], acc0[s]);
                acc1[s] = ffma2(v1p, cp[s], acc1[s]);
            }
        }
        if (it < NTILE - 1) {
            STS_TILE(cur ^ 1);
            if (it < NTILE - 2) LDG_TILE((it + 2) * ETILE);
            __syncthreads();
        }
    }

    int ta = t0 + tid;
    if (ta < T_DATA) {
#pragma unroll
        for (int s = 0; s < 10; s++) {
            float2 f = upk2(acc0[s]);
            g_syn[((size_t)b * SUB_NO + 2 * s)     * T_DATA + ta] = f.x;
            g_syn[((size_t)b * SUB_NO + 2 * s + 1) * T_DATA + ta] = f.y;
        }
    }
    int tb = t0 + GTHR + tid;
    if (tb < T_DATA) {
#pragma unroll
        for (int s = 0; s < 10; s++) {
            float2 f = upk2(acc1[s]);
            g_syn[((size_t)b * SUB_NO + 2 * s)     * T_DATA + tb] = f.x;
            g_syn[((size_t)b * SUB_NO + 2 * s + 1) * T_DATA + tb] = f.y;
        }
    }
}

// ---------- 3. depthwise causal conv (time-halved: 320 blocks) ----------
#define CHALF 2500
__global__ void __launch_bounds__(256) conv_kernel(const float* __restrict__ W1) {
    const int bs = blockIdx.x;
    const int half = bs & 1;
    const int bsub = bs >> 1;
    const int b = bsub / SUB_NO, s = bsub % SUB_NO;
    const int t0 = half * CHALF;
    __shared__ float ss[T_NO - 1 + CHALF];
    const int tid = threadIdx.x;

    const float* sp = g_syn + ((size_t)b * SUB_NO + s) * T_DATA;
    for (int i = tid; i < T_NO - 1 + CHALF; i += 256) {
        int gt = t0 - (T_NO - 1) + i;
        ss[i] = (gt >= 0) ? sp[gt] : 0.0f;
    }
    __syncthreads();

    for (int h = 0; h < HID_NO; h++) {
        const int c = s * HID_NO + h;
        float w[T_NO];
#pragma unroll
        for (int i = 0; i < T_NO; i++) w[i] = __ldg(&W1[c * T_NO + i]);
        float* cp = g_conv + ((size_t)(b * SH_NO + c)) * T_DATA + t0;
        for (int t = tid; t < CHALF; t += 256) {
            float acc = 0.0f;
#pragma unroll
            for (int tau = 0; tau < T_NO; tau++)
                acc = fmaf(ss[T_NO - 1 + t - tau], w[tau], acc);
            cp[t] = acc;
        }
    }
}

// ---------- 4. recurrence: R5-exact lockstep 4-warp pipeline (proven 332us) ----------
// W0(A): taps 1..19 serial; W1: 20..29 + conv; W2: 30..39 + stores; W3: 40..50.
template<int TB0, int NT, int WD, int MODE>
__device__ __forceinline__ void run_helper(
    int lane, int ch, int c,
    const float* __restrict__ Wh, const float* __restrict__ b1,
    const float* __restrict__ W2l,
    ull (*s_y)[32][7], ull (*sp)[32][7])
{
    float w[NT];
#pragma unroll
    for (int u = 0; u < NT; u++) w[u] = __ldg(&Wh[c * T_NO + TB0 + u - 1]);
    const float bias = (MODE == 1) ? b1[c] : 0.0f;
    const float ew2  = (MODE == 2) ? expf(W2l[c]) : 0.0f;
    const float* cv = g_conv + (size_t)ch * T_DATA;
    float* yo = g_ybuf + (size_t)ch * T_DATA;

    float yw[WD];
#pragma unroll
    for (int i = 0; i < WD; i++) yw[i] = 0.0f;

    float cn[10];
    // prologue: P[0]
    if (MODE == 1) {
        float c0[10];
#pragma unroll
        for (int j = 0; j < 10; j += 2) {
            float2 t = *(const float2*)(cv + j);
            c0[j] = t.x; c0[j + 1] = t.y;
        }
        float* pr = (float*)&sp[0][lane][0];
#pragma unroll
        for (int j = 0; j < 10; j++) pr[j] = c0[j] + bias;
#pragma unroll
        for (int j = 0; j < 10; j += 2) {
            float2 t = *(const float2*)(cv + PCH + j);
            cn[j] = t.x; cn[j + 1] = t.y;
        }
    } else {
        float* pr = (float*)&sp[0][lane][0];
#pragma unroll
        for (int j = 0; j < 10; j++) pr[j] = 0.0f;
    }
    __syncthreads();                       // bar 0

    // peeled k=0: P[1] (zero history)
    {
        float* pr = (float*)&sp[1][lane][0];
        if (MODE == 1) {
#pragma unroll
            for (int j = 0; j < 10; j++) pr[j] = cn[j] + bias;
#pragma unroll
            for (int j = 0; j < 10; j += 2) {
                float2 t = *(const float2*)(cv + 2 * PCH + j);
                cn[j] = t.x; cn[j + 1] = t.y;
            }
        } else {
#pragma unroll
            for (int j = 0; j < 10; j++) pr[j] = 0.0f;
        }
    }
    __syncthreads();                       // bar 1

    for (int k = 1; k <= NCHUNKS - 2; k++) {
        float yn[10];
        {
            const ull* yr = &s_y[(k - 1) & 1][lane][0];
#pragma unroll
            for (int q = 0; q < 5; q++) {
                float2 t = upk2(yr[q]);
                yn[2 * q] = t.x; yn[2 * q + 1] = t.y;
            }
        }
        if (MODE == 2) {
            float* yob = yo + (size_t)(k - 1) * PCH;
#pragma unroll
            for (int q = 0; q < 5; q++)
                *(float2*)(yob + 2 * q) =
                    make_float2(ew2 * yn[2 * q], ew2 * yn[2 * q + 1]);
        }
#pragma unroll
        for (int i = 0; i < WD - 10; i++) yw[i] = yw[i + 10];
#pragma unroll
        for (int j = 0; j < 10; j++) yw[WD - 10 + j] = yn[j];

        float part[10];
        if (MODE == 1) {
#pragma unroll
            for (int j = 0; j < 10; j++) part[j] = cn[j] + bias;
            int nidx = (k + 2 <= NCHUNKS - 1) ? (k + 2) : (NCHUNKS - 1);
#pragma unroll
            for (int j = 0; j < 10; j += 2) {
                float2 t = *(const float2*)(cv + nidx * PCH + j);
                cn[j] = t.x; cn[j + 1] = t.y;
            }
        } else {
#pragma unroll
            for (int j = 0; j < 10; j++) part[j] = 0.0f;
        }
#pragma unroll
        for (int j = 0; j < 10; j++)
#pragma unroll
            for (int u = 0; u < NT; u++)
                part[j] = fmaf(yw[WD + 10 + j - TB0 - u], w[u], part[j]);

        float* pw = (float*)&sp[(k + 1) & 1][lane][0];
#pragma unroll
        for (int j = 0; j < 10; j++) pw[j] = part[j];
        __syncthreads();                   // bars 2..499
    }

    if (MODE == 2) {
        const ull* yr = &s_y[(NCHUNKS - 2) & 1][lane][0];
        float* yob = yo + (size_t)(NCHUNKS - 2) * PCH;
#pragma unroll
        for (int q = 0; q < 5; q++) {
            float2 t = upk2(yr[q]);
            *(float2*)(yob + 2 * q) = make_float2(ew2 * t.x, ew2 * t.y);
        }
    }
    __syncthreads();                       // bar 500
    if (MODE == 2) {
        const ull* yr = &s_y[(NCHUNKS - 1) & 1][lane][0];
        float* yob = yo + (size_t)(NCHUNKS - 1) * PCH;
#pragma unroll
        for (int q = 0; q < 5; q++) {
            float2 t = upk2(yr[q]);
            *(float2*)(yob + 2 * q) = make_float2(ew2 * t.x, ew2 * t.y);
        }
    }
}

__global__ void __launch_bounds__(128, 1) recur_kernel(const float* __restrict__ Wh,
                                                       const float* __restrict__ b1,
                                                       const float* __restrict__ W2l) {
    __shared__ ull s_y[2][32][7];
    __shared__ ull s_p1[2][32][7];
    __shared__ ull s_p2[2][32][7];
    __shared__ ull s_p3[2][32][7];

    const int lane = threadIdx.x & 31;
    const int warp = threadIdx.x >> 5;
    const int ch = blockIdx.x * 32 + lane;
    const int c = ch % SH_NO;

    if (warp == 0) {
        float w[21];
#pragma unroll
        for (int i = 0; i < 19; i++) w[i] = __ldg(&Wh[c * T_NO + i]);
        w[19] = 0.0f; w[20] = 0.0f;
        ull wp0[10], wp1[10];
#pragma unroll
        for (int i = 0; i < 10; i++) {
            wp0[i] = pk2(w[2 * i], w[2 * i + 1]);
            wp1[i] = pk2(w[2 * i + 1], w[2 * i + 2]);
        }

        ull A2[15];
#pragma unroll
        for (int m = 0; m < 15; m++) A2[m] = 0ull;

        __syncthreads();                   // bar 0

        for (int k = 0; k < NCHUNKS; k++) {
            const ull* pp1 = &s_p1[k & 1][lane][0];
            const ull* pp2 = &s_p2[k & 1][lane][0];
            const ull* pp3 = &s_p3[k & 1][lane][0];
#pragma unroll
            for (int m = 0; m < 5; m++)
                A2[m] = add2(A2[m], add2(add2(pp1[m], pp2[m]), pp3[m]));

            ull* yrow = &s_y[k & 1][lane][0];
#pragma unroll
            for (int pp = 0; pp < 5; pp++) {
                float2 a = upk2(A2[pp]);
                float y0 = tanh_hw(a.x);
                float v1 = fmaf(y0, w[0], a.y);
                float y1 = tanh_hw(v1);
                yrow[pp] = pk2(y0, y1);
                ull yy0 = pk2(y0, y0);
                ull yy1 = pk2(y1, y1);
#pragma unroll
                for (int i = 0; i < 10; i++)
                    A2[pp + 1 + i] = ffma2(yy0, wp1[i],
                                     ffma2(yy1, wp0[i], A2[pp + 1 + i]));
            }
#pragma unroll
            for (int m = 0; m < 10; m++) A2[m] = A2[m + 5];
#pragma unroll
            for (int m = 10; m < 15; m++) A2[m] = 0ull;
            __syncthreads();               // bars 1..500
        }
    } else if (warp == 1) {
        run_helper<20, 10, 19, 1>(lane, ch, c, Wh, b1, W2l, s_y, s_p1);
    } else if (warp == 2) {
        run_helper<30, 10, 29, 2>(lane, ch, c, Wh, b1, W2l, s_y, s_p2);
    } else {
        run_helper<40, 11, 40, 0>(lane, ch, c, Wh, b1, W2l, s_y, s_p3);
    }
}

// ---------- 5. reduce ----------
__global__ void __launch_bounds__(256) reduce_kernel(const float* __restrict__ V_o,
                                                     float* __restrict__ out) {
    int idx = blockIdx.x * 256 + threadIdx.x;
    if (idx >= B_NO * T_DATA) return;
    int b = idx / T_DATA, t = idx % T_DATA;
    const float* p = g_ybuf + (size_t)b * SH_NO * T_DATA + t;
    float a = V_o[0];
#pragma unroll 10
    for (int c = 0; c < SH_NO; c++) a += p[(size_t)c * T_DATA];
    out[idx] = a;
}

extern "C" void kernel_launch(void* const* d_in, const int* in_sizes, int n_in,
                              void* d_out, int out_size) {
    const float* S_e     = (const float*)d_in[0];
    const float* C_syn_e = (const float*)d_in[2];
    const float* E_scale = (const float*)d_in[4];
    const float* W1      = (const float*)d_in[6];
    const float* W2      = (const float*)d_in[7];
    const float* b1      = (const float*)d_in[8];
    const float* Wh      = (const float*)d_in[9];
    const float* V_o     = (const float*)d_in[11];
    float* out = (float*)d_out;

    prep_kernel<<<(E_NO * SUB_NO + 255) / 256, 256>>>(C_syn_e, E_scale);
    dim3 gg((T_DATA + GROWS - 1) / GROWS, B_NO);
    gemm_kernel<<<gg, GTHR>>>(S_e);
    conv_kernel<<<B_NO * SUB_NO * 2, 256>>>(W1);
    recur_kernel<<<NCH / 32, 128>>>(Wh, b1, W2);
    reduce_kernel<<<(B_NO * T_DATA + 255) / 256, 256>>>(V_o, out);
}